// round 16
// baseline (speedup 1.0000x reference)
#include <cuda_runtime.h>
#include <math.h>

#define TT 1024
#define BB 4
#define DD 512
#define HH 8
#define TP 1152
#define LCW 128
#define NEGINF (__int_as_float(0xff800000))

// ---------------- scratch (static device memory) ----------------
#define OFF_XBUF  0UL          // 4*1024*512 = 2097152
#define OFF_YBUF  2097152UL    // 2097152
#define OFF_QBUF  4194304UL    // 4608*512   = 2359296
#define OFF_KVBUF 6553600UL    // 4608*256   = 1179648
#define OFF_QREL  7733248UL    // 36864*383  = 14118912
#define OFF_OBUF  21852160UL   // 2097152
#define OFF_HBUF  23949312UL   // 8388608
#define OFF_GBUF  32337920UL   // 4194304
#define OFF_KVW   36532224UL   // 4*256*512  = 524288
#define OFF_PW1P  37056512UL   // 4*1024*512 = 2097152
#define OFF_W1P   39153664UL   // 4*2048*512 = 4194304
#define SCR_TOTAL 43347968UL

__device__ float g_scr[SCR_TOTAL];

// ---------------- cp.async / ldmatrix helpers ----------------
__device__ __forceinline__ void cpa16(void* smem, const void* g) {
    unsigned s = (unsigned)__cvta_generic_to_shared(smem);
    asm volatile("cp.async.ca.shared.global [%0], [%1], 16;" :: "r"(s), "l"(g));
}
__device__ __forceinline__ void cpa16p(void* smem, const void* g, bool pred) {
    unsigned s = (unsigned)__cvta_generic_to_shared(smem);
    int sz = pred ? 16 : 0;
    asm volatile("cp.async.ca.shared.global [%0], [%1], 16, %2;" :: "r"(s), "l"(g), "r"(sz));
}
__device__ __forceinline__ void cp_commit() {
    asm volatile("cp.async.commit_group;");
}
template <int N>
__device__ __forceinline__ void cp_wait() {
    asm volatile("cp.async.wait_group %0;" :: "n"(N));
}
__device__ __forceinline__ void ldm_x4(unsigned& r0, unsigned& r1, unsigned& r2, unsigned& r3,
                                       const void* p) {
    unsigned a = (unsigned)__cvta_generic_to_shared(p);
    asm volatile("ldmatrix.sync.aligned.m8n8.x4.shared.b16 {%0,%1,%2,%3}, [%4];"
                 : "=r"(r0), "=r"(r1), "=r"(r2), "=r"(r3) : "r"(a));
}
__device__ __forceinline__ void mma_tf32(float* c, const unsigned* a, const unsigned* b) {
    asm volatile(
        "mma.sync.aligned.m16n8k8.row.col.f32.tf32.tf32.f32 "
        "{%0,%1,%2,%3}, {%4,%5,%6,%7}, {%8,%9}, {%0,%1,%2,%3};"
        : "+f"(c[0]), "+f"(c[1]), "+f"(c[2]), "+f"(c[3])
        : "r"(a[0]), "r"(a[1]), "r"(a[2]), "r"(a[3]), "r"(b[0]), "r"(b[1]));
}

// ---------------- pack K/V weights: kvw[l][256][512] ----------------
__global__ void pack_kv(const float* __restrict__ wk, const float* __restrict__ wv,
                        float* __restrict__ kvw)
{
    int i = blockIdx.x * 256 + threadIdx.x;
    if (i >= 4 * 256 * 512) return;
    int l = i / (256 * 512);
    int r = (i / 512) % 256;
    int c = i % 512;
    float v = (r < 128) ? wk[(size_t)l * 128 * 512 + r * 512 + c]
                        : wv[(size_t)l * 128 * 512 + (r - 128) * 512 + c];
    kvw[i] = v;
}

// ---------------- interleave GLU weight halves ----------------
__global__ void pack_glu(const float* __restrict__ w, float* __restrict__ wp,
                         int half, int total)
{
    int i = blockIdx.x * 256 + threadIdx.x;
    if (i >= total) return;
    int per = 2 * half * 512;
    int l = i / per;
    int rem = i - l * per;
    int r = rem / 512;
    int c = rem - r * 512;
    int src = (r & 1) ? (half + (r >> 1)) : (r >> 1);
    wp[i] = w[(size_t)l * per + (size_t)src * 512 + c];
}

// ---------------- LayerNorm ----------------
__global__ __launch_bounds__(128) void ln_kernel(
    const float* __restrict__ x, const float* __restrict__ w,
    const float* __restrict__ bvec, float* __restrict__ out)
{
    __shared__ float red[8];
    int r = blockIdx.x;
    int tid = threadIdx.x;
    const float* xr = x + (size_t)r * DD;
    float4 v = *(const float4*)(xr + tid * 4);
    float s  = v.x + v.y + v.z + v.w;
    float sq = v.x * v.x + v.y * v.y + v.z * v.z + v.w * v.w;
#pragma unroll
    for (int o = 16; o > 0; o >>= 1) {
        s  += __shfl_xor_sync(0xffffffffu, s, o);
        sq += __shfl_xor_sync(0xffffffffu, sq, o);
    }
    int warp = tid >> 5;
    if ((tid & 31) == 0) { red[warp] = s; red[4 + warp] = sq; }
    __syncthreads();
    float ts = red[0] + red[1] + red[2] + red[3];
    float tq = red[4] + red[5] + red[6] + red[7];
    float mean = ts * (1.f / DD);
    float var  = tq * (1.f / DD) - mean * mean;
    float inv  = rsqrtf(var + 1e-4f);
    float4 wv = *(const float4*)(w + tid * 4);
    float4 bv = *(const float4*)(bvec + tid * 4);
    float4 o;
    o.x = (v.x - mean) * inv * wv.x + bv.x;
    o.y = (v.y - mean) * inv * wv.y + bv.y;
    o.z = (v.z - mean) * inv * wv.z + bv.z;
    o.w = (v.w - mean) * inv * wv.w + bv.w;
    *(float4*)(out + (size_t)r * DD + tid * 4) = o;
}

// ---------------- TF32 tensor-core GEMM, 3-stage cp.async + ldmatrix ----------------
// mode 0: C = alpha*A@B^T (+Res), N guarded
// mode 1: GLU epilogue   mode 2: SwiGLU epilogue
// apad 1: A rows are padded-time rows: m -> (b = m/1152, t = m%1152);
//         t < 128 reads zero, else A row b*1024 + (t-128) (A stride = K).
__global__ __launch_bounds__(256) void gemm_tc(
    const float* __restrict__ A, const float* __restrict__ B,
    float* __restrict__ C, const float* __restrict__ Res,
    int M, int N, int K, float alpha, int mode, int apad)
{
    __shared__ float As[3][128][20];
    __shared__ float Bs[3][64][20];

    int tid = threadIdx.x;
    int bm = blockIdx.y * 128;
    int bn = blockIdx.x * 64;
    int wid = tid >> 5, lane = tid & 31;
    int wm = wid & 3, wn = wid >> 2;
    int gid = lane >> 2, tig = lane & 3;

    float acc[2][4][4];
#pragma unroll
    for (int i = 0; i < 2; i++)
#pragma unroll
        for (int j = 0; j < 4; j++)
#pragma unroll
            for (int q = 0; q < 4; q++) acc[i][j][q] = 0.f;

    int ar[2], ac[2];
    bool apred[2];
#pragma unroll
    for (int i = 0; i < 2; i++) {
        int idx = tid + i * 256;
        ar[i] = idx >> 2;
        ac[i] = (idx & 3) * 4;
        apred[i] = true;
    }
    int brow = tid >> 2;
    int bc   = (tid & 3) * 4;
    bool bpred = (bn + brow < N);

    const float* ap[2];
#pragma unroll
    for (int i = 0; i < 2; i++) {
        int row = bm + ar[i];
        if (apad) {
            int b = row / TP;
            int t = row - b * TP;
            apred[i] = (t >= LCW);
            int src = apred[i] ? (b * TT + (t - LCW)) : 0;
            ap[i] = A + (size_t)src * K + ac[i];
        } else {
            ap[i] = A + (size_t)row * K + ac[i];
        }
    }
    const float* bp = B + (size_t)(bn + brow) * K + bc;

    int nIters = K >> 4;
    int aRow = lane & 15;
    int aCol = (lane < 16) ? 0 : 4;

    cpa16p(&As[0][ar[0]][ac[0]], ap[0], apred[0]);
    cpa16p(&As[0][ar[1]][ac[1]], ap[1], apred[1]);
    cpa16p(&Bs[0][brow][bc], bp, bpred);
    cp_commit();
    if (nIters > 1) {
        cpa16p(&As[1][ar[0]][ac[0]], ap[0] + 16, apred[0]);
        cpa16p(&As[1][ar[1]][ac[1]], ap[1] + 16, apred[1]);
        cpa16p(&Bs[1][brow][bc], bp + 16, bpred);
    }
    cp_commit();

    for (int t = 0; t < nIters; t++) {
        cp_wait<1>();
        __syncthreads();
        if (t + 2 < nIters) {
            int k0 = (t + 2) << 4;
            int st = (t + 2) % 3;
            cpa16p(&As[st][ar[0]][ac[0]], ap[0] + k0, apred[0]);
            cpa16p(&As[st][ar[1]][ac[1]], ap[1] + k0, apred[1]);
            cpa16p(&Bs[st][brow][bc], bp + k0, bpred);
        }
        cp_commit();

        int cur = t % 3;
        const float (*Ac)[20] = As[cur];
        const float (*Bc)[20] = Bs[cur];
#pragma unroll
        for (int ks = 0; ks < 2; ks++) {
            int kk = ks * 8;
            unsigned a0f[4], a1f[4], bL[4], bH[4];
            ldm_x4(a0f[0], a0f[1], a0f[2], a0f[3], &Ac[wm * 32 + aRow][kk + aCol]);
            ldm_x4(a1f[0], a1f[1], a1f[2], a1f[3], &Ac[wm * 32 + 16 + aRow][kk + aCol]);
            ldm_x4(bL[0], bL[1], bL[2], bL[3], &Bc[wn * 32 + lane][kk]);
            ldm_x4(bH[0], bH[1], bH[2], bH[3], &Bc[wn * 32 + lane][kk + 4]);
#pragma unroll
            for (int nt = 0; nt < 4; nt++) {
                unsigned bb[2] = { bL[nt], bH[nt] };
                mma_tf32(acc[0][nt], a0f, bb);
                mma_tf32(acc[1][nt], a1f, bb);
            }
        }
    }

    if (mode == 0) {
#pragma unroll
        for (int mt = 0; mt < 2; mt++) {
            int r0 = bm + wm * 32 + mt * 16 + gid;
            int r1 = r0 + 8;
#pragma unroll
            for (int nt = 0; nt < 4; nt++) {
                int col0 = bn + wn * 32 + nt * 8 + tig * 2;
                int col1 = col0 + 1;
                float v0 = acc[mt][nt][0] * alpha;
                float v1 = acc[mt][nt][1] * alpha;
                float v2 = acc[mt][nt][2] * alpha;
                float v3 = acc[mt][nt][3] * alpha;
                if (col0 < N) {
                    if (Res) { v0 += Res[(size_t)r0 * N + col0]; v2 += Res[(size_t)r1 * N + col0]; }
                    C[(size_t)r0 * N + col0] = v0;
                    C[(size_t)r1 * N + col0] = v2;
                }
                if (col1 < N) {
                    if (Res) { v1 += Res[(size_t)r0 * N + col1]; v3 += Res[(size_t)r1 * N + col1]; }
                    C[(size_t)r0 * N + col1] = v1;
                    C[(size_t)r1 * N + col1] = v3;
                }
            }
        }
    } else {
        int No = N >> 1;
#pragma unroll
        for (int mt = 0; mt < 2; mt++) {
            int r0 = bm + wm * 32 + mt * 16 + gid;
            int r1 = r0 + 8;
#pragma unroll
            for (int nt = 0; nt < 4; nt++) {
                int col0 = bn + wn * 32 + nt * 8 + tig * 2;
                int outc = col0 >> 1;
                float h0 = acc[mt][nt][0], g0 = acc[mt][nt][1];
                float h2 = acc[mt][nt][2], g2 = acc[mt][nt][3];
                float o0, o2;
                if (mode == 1) {
                    o0 = h0 / (1.f + expf(-g0));
                    o2 = h2 / (1.f + expf(-g2));
                } else {
                    o0 = h0 / (1.f + expf(-h0)) * g0;
                    o2 = h2 / (1.f + expf(-h2)) * g2;
                }
                C[(size_t)r0 * No + outc] = o0;
                C[(size_t)r1 * No + outc] = o2;
            }
        }
    }
}

// ---------------- Windowed attention (valid rows), tf32 tensor cores ----------------
__global__ __launch_bounds__(256) void win_attn(
    const float* __restrict__ qb, const float* __restrict__ kv,
    const float* __restrict__ qrel, const int* __restrict__ alen,
    float* __restrict__ ob)
{
    extern __shared__ float sm[];
    float* Qs = sm;                    // 64*68
    float* Ks = Qs + 64 * 68;          // 192*68
    float* Vt = Ks + 192 * 68;         // 64*196
    float* S  = Vt + 64 * 196;         // 64*196

    int c = blockIdx.x + 2;
    int h = blockIdx.y;
    int b = blockIdx.z;
    int cs = c * 64;
    int lim = alen[b] + LCW;
    if (cs >= lim) return;
    int tid = threadIdx.x;
    int g = h >> 2;
    int lane = tid & 31, wid = tid >> 5;
    int wm = wid & 3, wn = wid >> 2;
    int gid = lane >> 2, tig = lane & 3;
    int aRow = lane & 15, aCol = (lane < 16) ? 0 : 4;

    const float* qbase = qb + ((size_t)(b * TP + cs)) * DD + h * 64;
#pragma unroll
    for (int i = 0; i < 4; i++) {
        int e = tid + i * 256;
        int row = e >> 4, dq = (e & 15) * 4;
        float4 v = *(const float4*)(qbase + (size_t)row * DD + dq);
        Qs[row * 68 + dq + 0] = v.x; Qs[row * 68 + dq + 1] = v.y;
        Qs[row * 68 + dq + 2] = v.z; Qs[row * 68 + dq + 3] = v.w;
    }
    const float* kbase = kv + ((size_t)(b * TP + cs - 128)) * 256 + g * 64;
    const float* vbase = kbase + 128;
#pragma unroll
    for (int i = 0; i < 12; i++) {
        int e = tid + i * 256;
        int row = e >> 4, dq = (e & 15) * 4;
        float4 kk = *(const float4*)(kbase + (size_t)row * 256 + dq);
        Ks[row * 68 + dq + 0] = kk.x; Ks[row * 68 + dq + 1] = kk.y;
        Ks[row * 68 + dq + 2] = kk.z; Ks[row * 68 + dq + 3] = kk.w;
        float4 vv = *(const float4*)(vbase + (size_t)row * 256 + dq);
        Vt[(dq + 0) * 196 + row] = vv.x; Vt[(dq + 1) * 196 + row] = vv.y;
        Vt[(dq + 2) * 196 + row] = vv.z; Vt[(dq + 3) * 196 + row] = vv.w;
    }
    __syncthreads();

    float accS[12][4];
#pragma unroll
    for (int i = 0; i < 12; i++)
#pragma unroll
        for (int j = 0; j < 4; j++) accS[i][j] = 0.f;

#pragma unroll
    for (int ks = 0; ks < 8; ks++) {
        int kk = ks * 8;
        unsigned a[4];
        ldm_x4(a[0], a[1], a[2], a[3], &Qs[(wm * 16 + aRow) * 68 + kk + aCol]);
#pragma unroll
        for (int ng = 0; ng < 3; ng++) {
            int n0 = wn * 96 + ng * 32;
            unsigned bL[4], bH[4];
            ldm_x4(bL[0], bL[1], bL[2], bL[3], &Ks[(n0 + lane) * 68 + kk]);
            ldm_x4(bH[0], bH[1], bH[2], bH[3], &Ks[(n0 + lane) * 68 + kk + 4]);
#pragma unroll
            for (int t2 = 0; t2 < 4; t2++) {
                unsigned bb[2] = { bL[t2], bH[t2] };
                mma_tf32(accS[ng * 4 + t2], a, bb);
            }
        }
    }

    int r0 = wm * 16 + gid, r1 = r0 + 8;
    size_t qr0 = ((size_t)(b * TP + cs + r0) * HH + h) * 383;
    size_t qr1 = ((size_t)(b * TP + cs + r1) * HH + h) * 383;
#pragma unroll
    for (int nt = 0; nt < 12; nt++) {
        int c0 = wn * 96 + nt * 8 + tig * 2;
        int c1 = c0 + 1;
        int k0g = cs - 128 + c0;
        int k1g = k0g + 1;
        S[r0 * 196 + c0] = (k0g < lim) ? (accS[nt][0] + __ldg(&qrel[qr0 + 319 + r0 - c0])) : NEGINF;
        S[r0 * 196 + c1] = (k1g < lim) ? (accS[nt][1] + __ldg(&qrel[qr0 + 319 + r0 - c1])) : NEGINF;
        S[r1 * 196 + c0] = (k0g < lim) ? (accS[nt][2] + __ldg(&qrel[qr1 + 319 + r1 - c0])) : NEGINF;
        S[r1 * 196 + c1] = (k1g < lim) ? (accS[nt][3] + __ldg(&qrel[qr1 + 319 + r1 - c1])) : NEGINF;
    }
    __syncthreads();

#pragma unroll
    for (int rw = 0; rw < 8; rw++) {
        int r = wid * 8 + rw;
        float sv[6];
        float m = NEGINF;
#pragma unroll
        for (int t = 0; t < 6; t++) { sv[t] = S[r * 196 + lane + t * 32]; m = fmaxf(m, sv[t]); }
#pragma unroll
        for (int o = 16; o > 0; o >>= 1) m = fmaxf(m, __shfl_xor_sync(0xffffffffu, m, o));
        float ss = 0.f;
#pragma unroll
        for (int t = 0; t < 6; t++) { sv[t] = expf(sv[t] - m); ss += sv[t]; }
#pragma unroll
        for (int o = 16; o > 0; o >>= 1) ss += __shfl_xor_sync(0xffffffffu, ss, o);
        float inv = 1.f / ss;
#pragma unroll
        for (int t = 0; t < 6; t++) S[r * 196 + lane + t * 32] = sv[t] * inv;
    }
    __syncthreads();

    float accO[4][4];
#pragma unroll
    for (int i = 0; i < 4; i++)
#pragma unroll
        for (int j = 0; j < 4; j++) accO[i][j] = 0.f;

#pragma unroll
    for (int ks = 0; ks < 24; ks++) {
        int kk = ks * 8;
        unsigned a[4], bL[4], bH[4];
        ldm_x4(a[0], a[1], a[2], a[3], &S[(wm * 16 + aRow) * 196 + kk + aCol]);
        ldm_x4(bL[0], bL[1], bL[2], bL[3], &Vt[(wn * 32 + lane) * 196 + kk]);
        ldm_x4(bH[0], bH[1], bH[2], bH[3], &Vt[(wn * 32 + lane) * 196 + kk + 4]);
#pragma unroll
        for (int nt = 0; nt < 4; nt++) {
            unsigned bb[2] = { bL[nt], bH[nt] };
            mma_tf32(accO[nt], a, bb);
        }
    }

    int q0 = cs + r0, q1 = cs + r1;
#pragma unroll
    for (int nt = 0; nt < 4; nt++) {
        int d0 = wn * 32 + nt * 8 + tig * 2;
        if (q0 < lim) {
            float* op = ob + ((size_t)(b * TT + q0 - 128)) * DD + h * 64 + d0;
            op[0] = accO[nt][0]; op[1] = accO[nt][1];
        }
        if (q1 < lim) {
            float* op = ob + ((size_t)(b * TT + q1 - 128)) * DD + h * 64 + d0;
            op[0] = accO[nt][2]; op[1] = accO[nt][3];
        }
    }
}

// ---------------- Dense flash attention (invalid rows), tf32 tensor cores ----------------
__global__ __launch_bounds__(256) void dense_flash(
    const float* __restrict__ qb, const float* __restrict__ kv,
    const float* __restrict__ qrel, const int* __restrict__ alen,
    float* __restrict__ ob)
{
    extern __shared__ float sm[];
    float* Qs = sm;                    // 64*68
    float* Ks = Qs + 64 * 68;          // 128*68
    float* Vt = Ks + 128 * 68;         // 64*132
    float* S  = Vt + 64 * 132;         // 64*132
    float* rowm = S + 64 * 132;
    float* rowsum = rowm + 64;
    float* rowscale = rowsum + 64;

    int c = blockIdx.x + 2;
    int h = blockIdx.y;
    int b = blockIdx.z;
    int cs = c * 64;
    int lim = alen[b] + LCW;
    if (cs + 64 <= lim) return;
    int tid = threadIdx.x;
    int g = h >> 2;
    int lane = tid & 31, wid = tid >> 5;
    int wm = wid & 3, wn = wid >> 2;
    int gid = lane >> 2, tig = lane & 3;
    int aRow = lane & 15, aCol = (lane < 16) ? 0 : 4;
    int r0 = wm * 16 + gid, r1 = r0 + 8;

    const float* qbase = qb + ((size_t)(b * TP + cs)) * DD + h * 64;
#pragma unroll
    for (int i = 0; i < 4; i++) {
        int e = tid + i * 256;
        int row = e >> 4, dq = (e & 15) * 4;
        float4 v = *(const float4*)(qbase + (size_t)row * DD + dq);
        Qs[row * 68 + dq + 0] = v.x; Qs[row * 68 + dq + 1] = v.y;
        Qs[row * 68 + dq + 2] = v.z; Qs[row * 68 + dq + 3] = v.w;
    }
    if (tid < 64) { rowm[tid] = NEGINF; rowsum[tid] = 0.f; }

    float accO[4][4];
#pragma unroll
    for (int i = 0; i < 4; i++)
#pragma unroll
        for (int j = 0; j < 4; j++) accO[i][j] = 0.f;

    size_t qr0 = ((size_t)(b * TP + cs + r0) * HH + h) * 383;
    size_t qr1 = ((size_t)(b * TP + cs + r1) * HH + h) * 383;

    __syncthreads();

    for (int pg = 0; pg < 9; pg++) {
        const float* kp = kv + ((size_t)(b * TP + pg * 128)) * 256 + g * 64;
#pragma unroll
        for (int i = 0; i < 8; i++) {
            int e = tid + i * 256;
            int row = e >> 4, dq = (e & 15) * 4;
            float4 kk = *(const float4*)(kp + (size_t)row * 256 + dq);
            Ks[row * 68 + dq + 0] = kk.x; Ks[row * 68 + dq + 1] = kk.y;
            Ks[row * 68 + dq + 2] = kk.z; Ks[row * 68 + dq + 3] = kk.w;
            float4 vv = *(const float4*)(kp + (size_t)row * 256 + 128 + dq);
            Vt[(dq + 0) * 132 + row] = vv.x; Vt[(dq + 1) * 132 + row] = vv.y;
            Vt[(dq + 2) * 132 + row] = vv.z; Vt[(dq + 3) * 132 + row] = vv.w;
        }
        __syncthreads();

        float accS[8][4];
#pragma unroll
        for (int i = 0; i < 8; i++)
#pragma unroll
            for (int j = 0; j < 4; j++) accS[i][j] = 0.f;
#pragma unroll
        for (int ks = 0; ks < 8; ks++) {
            int kk = ks * 8;
            unsigned a[4];
            ldm_x4(a[0], a[1], a[2], a[3], &Qs[(wm * 16 + aRow) * 68 + kk + aCol]);
#pragma unroll
            for (int ng = 0; ng < 2; ng++) {
                int n0 = wn * 64 + ng * 32;
                unsigned bL[4], bH[4];
                ldm_x4(bL[0], bL[1], bL[2], bL[3], &Ks[(n0 + lane) * 68 + kk]);
                ldm_x4(bH[0], bH[1], bH[2], bH[3], &Ks[(n0 + lane) * 68 + kk + 4]);
#pragma unroll
                for (int t2 = 0; t2 < 4; t2++) {
                    unsigned bb[2] = { bL[t2], bH[t2] };
                    mma_tf32(accS[ng * 4 + t2], a, bb);
                }
            }
        }
#pragma unroll
        for (int nt = 0; nt < 8; nt++) {
            int c0 = wn * 64 + nt * 8 + tig * 2;
            int c1 = c0 + 1;
            int k0 = pg * 128 + c0, k1 = k0 + 1;
            int d00 = max(-191, min(191, cs + r0 - k0));
            int d01 = max(-191, min(191, cs + r0 - k1));
            int d10 = max(-191, min(191, cs + r1 - k0));
            int d11 = max(-191, min(191, cs + r1 - k1));
            S[r0 * 132 + c0] = accS[nt][0] + __ldg(&qrel[qr0 + 191 + d00]);
            S[r0 * 132 + c1] = accS[nt][1] + __ldg(&qrel[qr0 + 191 + d01]);
            S[r1 * 132 + c0] = accS[nt][2] + __ldg(&qrel[qr1 + 191 + d10]);
            S[r1 * 132 + c1] = accS[nt][3] + __ldg(&qrel[qr1 + 191 + d11]);
        }
        __syncthreads();

#pragma unroll
        for (int rw = 0; rw < 8; rw++) {
            int r = wid * 8 + rw;
            float v0 = S[r * 132 + lane];
            float v1 = S[r * 132 + lane + 32];
            float v2 = S[r * 132 + lane + 64];
            float v3 = S[r * 132 + lane + 96];
            float mn = fmaxf(fmaxf(v0, v1), fmaxf(v2, v3));
#pragma unroll
            for (int o = 16; o > 0; o >>= 1) mn = fmaxf(mn, __shfl_xor_sync(0xffffffffu, mn, o));
            float mo = rowm[r];
            float mp = fmaxf(mo, mn);
            float p0 = expf(v0 - mp), p1 = expf(v1 - mp), p2 = expf(v2 - mp), p3 = expf(v3 - mp);
            S[r * 132 + lane] = p0; S[r * 132 + lane + 32] = p1;
            S[r * 132 + lane + 64] = p2; S[r * 132 + lane + 96] = p3;
            float ss = p0 + p1 + p2 + p3;
#pragma unroll
            for (int o = 16; o > 0; o >>= 1) ss += __shfl_xor_sync(0xffffffffu, ss, o);
            if (lane == 0) {
                float scale = expf(mo - mp);
                rowm[r] = mp;
                rowscale[r] = scale;
                rowsum[r] = rowsum[r] * scale + ss;
            }
        }
        __syncthreads();

        float sc0 = rowscale[r0], sc1 = rowscale[r1];
#pragma unroll
        for (int nt = 0; nt < 4; nt++) {
            accO[nt][0] *= sc0; accO[nt][1] *= sc0;
            accO[nt][2] *= sc1; accO[nt][3] *= sc1;
        }
#pragma unroll
        for (int ks = 0; ks < 16; ks++) {
            int kk = ks * 8;
            unsigned a[4], bL[4], bH[4];
            ldm_x4(a[0], a[1], a[2], a[3], &S[(wm * 16 + aRow) * 132 + kk + aCol]);
            ldm_x4(bL[0], bL[1], bL[2], bL[3], &Vt[(wn * 32 + lane) * 132 + kk]);
            ldm_x4(bH[0], bH[1], bH[2], bH[3], &Vt[(wn * 32 + lane) * 132 + kk + 4]);
#pragma unroll
            for (int nt = 0; nt < 4; nt++) {
                unsigned bb[2] = { bL[nt], bH[nt] };
                mma_tf32(accO[nt], a, bb);
            }
        }
        __syncthreads();
    }

    int q0 = cs + r0, q1 = cs + r1;
    float inv0 = 1.f / rowsum[r0];
    float inv1 = 1.f / rowsum[r1];
#pragma unroll
    for (int nt = 0; nt < 4; nt++) {
        int d0 = wn * 32 + nt * 8 + tig * 2;
        if (q0 >= lim) {
            float* op = ob + ((size_t)(b * TT + q0 - 128)) * DD + h * 64 + d0;
            op[0] = accO[nt][0] * inv0; op[1] = accO[nt][1] * inv0;
        }
        if (q1 >= lim) {
            float* op = ob + ((size_t)(b * TT + q1 - 128)) * DD + h * 64 + d0;
            op[0] = accO[nt][2] * inv1; op[1] = accO[nt][3] * inv1;
        }
    }
}

// ---------------- depthwise conv (k=9, pad 4) + SiLU ----------------
__global__ __launch_bounds__(128) void dwconv_silu(
    const float* __restrict__ in, const float* __restrict__ dw, float* __restrict__ out)
{
    int t = blockIdx.x, b = blockIdx.y;
    int d0 = threadIdx.x * 4;
    float w[9][4];
#pragma unroll
    for (int c = 0; c < 4; c++)
#pragma unroll
        for (int j = 0; j < 9; j++)
            w[j][c] = __ldg(&dw[(d0 + c) * 9 + j]);
    float4 acc = make_float4(0.f, 0.f, 0.f, 0.f);
#pragma unroll
    for (int j = 0; j < 9; j++) {
        int tt = t + j - 4;
        if (tt >= 0 && tt < TT) {
            float4 v = *(const float4*)(in + ((size_t)(b * TT + tt)) * DD + d0);
            acc.x += v.x * w[j][0];
            acc.y += v.y * w[j][1];
            acc.z += v.z * w[j][2];
            acc.w += v.w * w[j][3];
        }
    }
    acc.x = acc.x / (1.f + expf(-acc.x));
    acc.y = acc.y / (1.f + expf(-acc.y));
    acc.z = acc.z / (1.f + expf(-acc.z));
    acc.w = acc.w / (1.f + expf(-acc.w));
    *(float4*)(out + ((size_t)(b * TT + t)) * DD + d0) = acc;
}

// ---------------- orchestration ----------------
extern "C" void kernel_launch(void* const* d_in, const int* in_sizes, int n_in,
                              void* d_out, int out_size)
{
    const float* x_in  = (const float*)d_in[0];
    const int*   alen  = (const int*)d_in[1];
    const float* ln1_w = (const float*)d_in[2];
    const float* ln1_b = (const float*)d_in[3];
    const float* wq    = (const float*)d_in[4];
    const float* wk    = (const float*)d_in[5];
    const float* wv    = (const float*)d_in[6];
    const float* wo    = (const float*)d_in[7];
    const float* rel   = (const float*)d_in[8];
    const float* ln2_w = (const float*)d_in[9];
    const float* ln2_b = (const float*)d_in[10];
    const float* pw1   = (const float*)d_in[11];
    const float* dw    = (const float*)d_in[12];
    const float* pw2   = (const float*)d_in[13];
    const float* ln3_w = (const float*)d_in[14];
    const float* ln3_b = (const float*)d_in[15];
    const float* w1    = (const float*)d_in[16];
    const float* w2    = (const float*)d_in[17];

    float* scr = nullptr;
    cudaGetSymbolAddress((void**)&scr, g_scr);
    float* xbuf  = scr + OFF_XBUF;
    float* ybuf  = scr + OFF_YBUF;
    float* qbuf  = scr + OFF_QBUF;
    float* kvbuf = scr + OFF_KVBUF;
    float* qrlb  = scr + OFF_QREL;
    float* obuf  = scr + OFF_OBUF;
    float* hbuf  = scr + OFF_HBUF;
    float* gbuf  = scr + OFF_GBUF;
    float* kvw   = scr + OFF_KVW;
    float* pw1p  = scr + OFF_PW1P;
    float* w1p   = scr + OFF_W1P;

    const int WIN_SMEM = (64 * 68 + 192 * 68 + 64 * 196 + 64 * 196) * 4;
    const int DF_SMEM  = (64 * 68 + 128 * 68 + 64 * 132 + 64 * 132 + 192) * 4;
    cudaFuncSetAttribute(win_attn, cudaFuncAttributeMaxDynamicSharedMemorySize, WIN_SMEM);
    cudaFuncSetAttribute(dense_flash, cudaFuncAttributeMaxDynamicSharedMemorySize, DF_SMEM);

    pack_kv<<<(4 * 256 * 512 + 255) / 256, 256>>>(wk, wv, kvw);
    pack_glu<<<(4 * 1024 * 512 + 255) / 256, 256>>>(pw1, pw1p, 512, 4 * 1024 * 512);
    pack_glu<<<(4 * 2048 * 512 + 255) / 256, 256>>>(w1, w1p, 1024, 4 * 2048 * 512);

    for (int l = 0; l < 4; l++) {
        const float* src = (l == 0) ? x_in : xbuf;
        // LN1 -> ybuf only; Q/KV GEMMs apply the pad remap on the A side (apad=1)
        ln_kernel<<<4096, 128>>>(src, ln1_w + l * 512, ln1_b + l * 512, ybuf);
        gemm_tc<<<dim3(8, 36), 256>>>(ybuf, wq + (size_t)l * 512 * 512, qbuf, nullptr, 4608, 512, 512, 0.125f, 0, 1);
        gemm_tc<<<dim3(4, 36), 256>>>(ybuf, kvw + (size_t)l * 256 * 512, kvbuf, nullptr, 4608, 256, 512, 1.f, 0, 1);
        gemm_tc<<<dim3(6, 288), 256>>>(qbuf, rel + (size_t)l * 383 * 64, qrlb, nullptr, 36864, 383, 64, 1.f, 0, 0);
        win_attn<<<dim3(16, 8, 4), 256, WIN_SMEM>>>(qbuf, kvbuf, qrlb, alen, obuf);
        dense_flash<<<dim3(16, 8, 4), 256, DF_SMEM>>>(qbuf, kvbuf, qrlb, alen, obuf);
        gemm_tc<<<dim3(8, 32), 256>>>(obuf, wo + (size_t)l * 512 * 512, xbuf, ybuf, 4096, 512, 512, 1.f, 0, 0);
        ln_kernel<<<4096, 128>>>(xbuf, ln2_w + l * 512, ln2_b + l * 512, ybuf);
        gemm_tc<<<dim3(16, 32), 256>>>(ybuf, pw1p + (size_t)l * 1024 * 512, gbuf, nullptr, 4096, 1024, 512, 1.f, 1, 0);
        dwconv_silu<<<dim3(1024, 4), 128>>>(gbuf, dw + (size_t)l * 512 * 9, hbuf);
        gemm_tc<<<dim3(8, 32), 256>>>(hbuf, pw2 + (size_t)l * 512 * 512, xbuf, ybuf, 4096, 512, 512, 1.f, 0, 0);
        ln_kernel<<<4096, 128>>>(xbuf, ln3_w + l * 512, ln3_b + l * 512, ybuf);
        gemm_tc<<<dim3(32, 32), 256>>>(ybuf, w1p + (size_t)l * 2048 * 512, gbuf, nullptr, 4096, 2048, 512, 1.f, 2, 0);
        float* dst = (l == 3) ? (float*)d_out : xbuf;
        gemm_tc<<<dim3(8, 32), 256>>>(gbuf, w2 + (size_t)l * 512 * 1024, dst, ybuf, 4096, 512, 1024, 1.f, 0, 0);
    }
}

// round 17
// speedup vs baseline: 1.0091x; 1.0091x over previous
#include <cuda_runtime.h>
#include <math.h>

#define TT 1024
#define BB 4
#define DD 512
#define HH 8
#define TP 1152
#define LCW 128
#define NEGINF (__int_as_float(0xff800000))

// ---------------- scratch (static device memory) ----------------
#define OFF_XPAD  0UL          // 4*1152*512  = 2359296
#define OFF_XBUF  2359296UL    // 2097152
#define OFF_YBUF  4456448UL    // 2097152
#define OFF_QBUF  6553600UL    // 4608*512    = 2359296
#define OFF_KVBUF 8912896UL    // 4608*256    = 1179648
#define OFF_QREL  10092544UL   // 36864*383   = 14118912
#define OFF_OBUF  24211456UL   // 2097152
#define OFF_HBUF  26308608UL   // 8388608
#define OFF_GBUF  34697216UL   // 4194304
#define OFF_KVW   38891520UL   // 4*256*512   = 524288
#define OFF_PW1P  39415808UL   // 4*1024*512  = 2097152
#define OFF_W1P   41512960UL   // 4*2048*512  = 4194304
#define SCR_TOTAL 45707264UL

__device__ float g_scr[SCR_TOTAL];

// ---------------- cp.async / ldmatrix helpers ----------------
__device__ __forceinline__ void cpa16(void* smem, const void* g) {
    unsigned s = (unsigned)__cvta_generic_to_shared(smem);
    asm volatile("cp.async.ca.shared.global [%0], [%1], 16;" :: "r"(s), "l"(g));
}
__device__ __forceinline__ void cpa16p(void* smem, const void* g, bool pred) {
    unsigned s = (unsigned)__cvta_generic_to_shared(smem);
    int sz = pred ? 16 : 0;
    asm volatile("cp.async.ca.shared.global [%0], [%1], 16, %2;" :: "r"(s), "l"(g), "r"(sz));
}
__device__ __forceinline__ void cp_commit() {
    asm volatile("cp.async.commit_group;");
}
template <int N>
__device__ __forceinline__ void cp_wait() {
    asm volatile("cp.async.wait_group %0;" :: "n"(N));
}
__device__ __forceinline__ void ldm_x4(unsigned& r0, unsigned& r1, unsigned& r2, unsigned& r3,
                                       const void* p) {
    unsigned a = (unsigned)__cvta_generic_to_shared(p);
    asm volatile("ldmatrix.sync.aligned.m8n8.x4.shared.b16 {%0,%1,%2,%3}, [%4];"
                 : "=r"(r0), "=r"(r1), "=r"(r2), "=r"(r3) : "r"(a));
}
__device__ __forceinline__ void mma_tf32(float* c, const unsigned* a, const unsigned* b) {
    asm volatile(
        "mma.sync.aligned.m16n8k8.row.col.f32.tf32.tf32.f32 "
        "{%0,%1,%2,%3}, {%4,%5,%6,%7}, {%8,%9}, {%0,%1,%2,%3};"
        : "+f"(c[0]), "+f"(c[1]), "+f"(c[2]), "+f"(c[3])
        : "r"(a[0]), "r"(a[1]), "r"(a[2]), "r"(a[3]), "r"(b[0]), "r"(b[1]));
}

// ---------------- zero the left-context pad rows of xpad ----------------
__global__ void zero_pad_kernel(float* __restrict__ xpad) {
    int i = blockIdx.x * 256 + threadIdx.x;
    if (i < BB * LCW * DD) {
        int b = i / (LCW * DD);
        int rem = i - b * (LCW * DD);
        xpad[(size_t)b * TP * DD + rem] = 0.f;
    }
}

// ---------------- pack K/V weights: kvw[l][256][512] ----------------
__global__ void pack_kv(const float* __restrict__ wk, const float* __restrict__ wv,
                        float* __restrict__ kvw)
{
    int i = blockIdx.x * 256 + threadIdx.x;
    if (i >= 4 * 256 * 512) return;
    int l = i / (256 * 512);
    int r = (i / 512) % 256;
    int c = i % 512;
    float v = (r < 128) ? wk[(size_t)l * 128 * 512 + r * 512 + c]
                        : wv[(size_t)l * 128 * 512 + (r - 128) * 512 + c];
    kvw[i] = v;
}

// ---------------- interleave GLU weight halves ----------------
__global__ void pack_glu(const float* __restrict__ w, float* __restrict__ wp,
                         int half, int total)
{
    int i = blockIdx.x * 256 + threadIdx.x;
    if (i >= total) return;
    int per = 2 * half * 512;
    int l = i / per;
    int rem = i - l * per;
    int r = rem / 512;
    int c = rem - r * 512;
    int src = (r & 1) ? (half + (r >> 1)) : (r >> 1);
    wp[i] = w[(size_t)l * per + (size_t)src * 512 + c];
}

// ---------------- LayerNorm ----------------
__global__ __launch_bounds__(128) void ln_kernel(
    const float* __restrict__ x, const float* __restrict__ w,
    const float* __restrict__ bvec, float* __restrict__ out,
    float* __restrict__ outpad)
{
    __shared__ float red[8];
    int r = blockIdx.x;
    int tid = threadIdx.x;
    const float* xr = x + (size_t)r * DD;
    float4 v = *(const float4*)(xr + tid * 4);
    float s  = v.x + v.y + v.z + v.w;
    float sq = v.x * v.x + v.y * v.y + v.z * v.z + v.w * v.w;
#pragma unroll
    for (int o = 16; o > 0; o >>= 1) {
        s  += __shfl_xor_sync(0xffffffffu, s, o);
        sq += __shfl_xor_sync(0xffffffffu, sq, o);
    }
    int warp = tid >> 5;
    if ((tid & 31) == 0) { red[warp] = s; red[4 + warp] = sq; }
    __syncthreads();
    float ts = red[0] + red[1] + red[2] + red[3];
    float tq = red[4] + red[5] + red[6] + red[7];
    float mean = ts * (1.f / DD);
    float var  = tq * (1.f / DD) - mean * mean;
    float inv  = rsqrtf(var + 1e-4f);
    float4 wv = *(const float4*)(w + tid * 4);
    float4 bv = *(const float4*)(bvec + tid * 4);
    float4 o;
    o.x = (v.x - mean) * inv * wv.x + bv.x;
    o.y = (v.y - mean) * inv * wv.y + bv.y;
    o.z = (v.z - mean) * inv * wv.z + bv.z;
    o.w = (v.w - mean) * inv * wv.w + bv.w;
    *(float4*)(out + (size_t)r * DD + tid * 4) = o;
    if (outpad) {
        int b = r >> 10, t = r & 1023;
        *(float4*)(outpad + ((size_t)(b * TP + LCW + t)) * DD + tid * 4) = o;
    }
}

// ---------------- TF32 tensor-core GEMM, 3-stage cp.async + ldmatrix ----------------
// mode 0: C = alpha*A@B^T (+Res), N guarded
// mode 1: GLU      out[., n] = h0*sigmoid(h1) on adjacent col pairs (N%64==0)
// mode 2: SwiGLU   out[., n] = silu(h0)*h1
__global__ __launch_bounds__(256) void gemm_tc(
    const float* __restrict__ A, const float* __restrict__ B,
    float* __restrict__ C, const float* __restrict__ Res,
    int M, int N, int K, float alpha, int mode)
{
    __shared__ float As[3][128][20];
    __shared__ float Bs[3][64][20];

    int tid = threadIdx.x;
    int bm = blockIdx.y * 128;
    int bn = blockIdx.x * 64;
    int wid = tid >> 5, lane = tid & 31;
    int wm = wid & 3, wn = wid >> 2;
    int gid = lane >> 2, tig = lane & 3;

    float acc[2][4][4];
#pragma unroll
    for (int i = 0; i < 2; i++)
#pragma unroll
        for (int j = 0; j < 4; j++)
#pragma unroll
            for (int q = 0; q < 4; q++) acc[i][j][q] = 0.f;

    int ar[2], ac[2];
#pragma unroll
    for (int i = 0; i < 2; i++) {
        int idx = tid + i * 256;
        ar[i] = idx >> 2;
        ac[i] = (idx & 3) * 4;
    }
    int brow = tid >> 2;
    int bc   = (tid & 3) * 4;
    bool bpred = (bn + brow < N);

    const float* ap0 = A + (size_t)(bm + ar[0]) * K + ac[0];
    const float* ap1 = A + (size_t)(bm + ar[1]) * K + ac[1];
    const float* bp  = B + (size_t)(bn + brow) * K + bc;

    int nIters = K >> 4;
    int aRow = lane & 15;
    int aCol = (lane < 16) ? 0 : 4;

    cpa16(&As[0][ar[0]][ac[0]], ap0);
    cpa16(&As[0][ar[1]][ac[1]], ap1);
    cpa16p(&Bs[0][brow][bc], bp, bpred);
    cp_commit();
    if (nIters > 1) {
        cpa16(&As[1][ar[0]][ac[0]], ap0 + 16);
        cpa16(&As[1][ar[1]][ac[1]], ap1 + 16);
        cpa16p(&Bs[1][brow][bc], bp + 16, bpred);
    }
    cp_commit();

    for (int t = 0; t < nIters; t++) {
        cp_wait<1>();
        __syncthreads();
        if (t + 2 < nIters) {
            int k0 = (t + 2) << 4;
            int st = (t + 2) % 3;
            cpa16(&As[st][ar[0]][ac[0]], ap0 + k0);
            cpa16(&As[st][ar[1]][ac[1]], ap1 + k0);
            cpa16p(&Bs[st][brow][bc], bp + k0, bpred);
        }
        cp_commit();

        int cur = t % 3;
        const float (*Ac)[20] = As[cur];
        const float (*Bc)[20] = Bs[cur];
#pragma unroll
        for (int ks = 0; ks < 2; ks++) {
            int kk = ks * 8;
            unsigned a0f[4], a1f[4], bL[4], bH[4];
            ldm_x4(a0f[0], a0f[1], a0f[2], a0f[3], &Ac[wm * 32 + aRow][kk + aCol]);
            ldm_x4(a1f[0], a1f[1], a1f[2], a1f[3], &Ac[wm * 32 + 16 + aRow][kk + aCol]);
            ldm_x4(bL[0], bL[1], bL[2], bL[3], &Bc[wn * 32 + lane][kk]);
            ldm_x4(bH[0], bH[1], bH[2], bH[3], &Bc[wn * 32 + lane][kk + 4]);
#pragma unroll
            for (int nt = 0; nt < 4; nt++) {
                unsigned bb[2] = { bL[nt], bH[nt] };
                mma_tf32(acc[0][nt], a0f, bb);
                mma_tf32(acc[1][nt], a1f, bb);
            }
        }
    }

    if (mode == 0) {
#pragma unroll
        for (int mt = 0; mt < 2; mt++) {
            int r0 = bm + wm * 32 + mt * 16 + gid;
            int r1 = r0 + 8;
#pragma unroll
            for (int nt = 0; nt < 4; nt++) {
                int col0 = bn + wn * 32 + nt * 8 + tig * 2;
                int col1 = col0 + 1;
                float v0 = acc[mt][nt][0] * alpha;
                float v1 = acc[mt][nt][1] * alpha;
                float v2 = acc[mt][nt][2] * alpha;
                float v3 = acc[mt][nt][3] * alpha;
                if (col0 < N) {
                    if (Res) { v0 += Res[(size_t)r0 * N + col0]; v2 += Res[(size_t)r1 * N + col0]; }
                    C[(size_t)r0 * N + col0] = v0;
                    C[(size_t)r1 * N + col0] = v2;
                }
                if (col1 < N) {
                    if (Res) { v1 += Res[(size_t)r0 * N + col1]; v3 += Res[(size_t)r1 * N + col1]; }
                    C[(size_t)r0 * N + col1] = v1;
                    C[(size_t)r1 * N + col1] = v3;
                }
            }
        }
    } else {
        int No = N >> 1;
#pragma unroll
        for (int mt = 0; mt < 2; mt++) {
            int r0 = bm + wm * 32 + mt * 16 + gid;
            int r1 = r0 + 8;
#pragma unroll
            for (int nt = 0; nt < 4; nt++) {
                int col0 = bn + wn * 32 + nt * 8 + tig * 2;
                int outc = col0 >> 1;
                float h0 = acc[mt][nt][0], g0 = acc[mt][nt][1];
                float h2 = acc[mt][nt][2], g2 = acc[mt][nt][3];
                float o0, o2;
                if (mode == 1) {
                    o0 = h0 / (1.f + expf(-g0));
                    o2 = h2 / (1.f + expf(-g2));
                } else {
                    o0 = h0 / (1.f + expf(-h0)) * g0;
                    o2 = h2 / (1.f + expf(-h2)) * g2;
                }
                C[(size_t)r0 * No + outc] = o0;
                C[(size_t)r1 * No + outc] = o2;
            }
        }
    }
}

// ---------------- Windowed attention (valid rows), tf32 tensor cores ----------------
__global__ __launch_bounds__(256) void win_attn(
    const float* __restrict__ qb, const float* __restrict__ kv,
    const float* __restrict__ qrel, const int* __restrict__ alen,
    float* __restrict__ ob)
{
    extern __shared__ float sm[];
    float* Qs = sm;                    // 64*68
    float* Ks = Qs + 64 * 68;          // 192*68
    float* Vt = Ks + 192 * 68;         // 64*196
    float* S  = Vt + 64 * 196;         // 64*196

    int c = blockIdx.x + 2;
    int h = blockIdx.y;
    int b = blockIdx.z;
    int cs = c * 64;
    int lim = alen[b] + LCW;
    if (cs >= lim) return;
    int tid = threadIdx.x;
    int g = h >> 2;
    int lane = tid & 31, wid = tid >> 5;
    int wm = wid & 3, wn = wid >> 2;
    int gid = lane >> 2, tig = lane & 3;
    int aRow = lane & 15, aCol = (lane < 16) ? 0 : 4;

    const float* qbase = qb + ((size_t)(b * TP + cs)) * DD + h * 64;
#pragma unroll
    for (int i = 0; i < 4; i++) {
        int e = tid + i * 256;
        int row = e >> 4, dq = (e & 15) * 4;
        float4 v = *(const float4*)(qbase + (size_t)row * DD + dq);
        Qs[row * 68 + dq + 0] = v.x; Qs[row * 68 + dq + 1] = v.y;
        Qs[row * 68 + dq + 2] = v.z; Qs[row * 68 + dq + 3] = v.w;
    }
    const float* kbase = kv + ((size_t)(b * TP + cs - 128)) * 256 + g * 64;
    const float* vbase = kbase + 128;
#pragma unroll
    for (int i = 0; i < 12; i++) {
        int e = tid + i * 256;
        int row = e >> 4, dq = (e & 15) * 4;
        float4 kk = *(const float4*)(kbase + (size_t)row * 256 + dq);
        Ks[row * 68 + dq + 0] = kk.x; Ks[row * 68 + dq + 1] = kk.y;
        Ks[row * 68 + dq + 2] = kk.z; Ks[row * 68 + dq + 3] = kk.w;
        float4 vv = *(const float4*)(vbase + (size_t)row * 256 + dq);
        Vt[(dq + 0) * 196 + row] = vv.x; Vt[(dq + 1) * 196 + row] = vv.y;
        Vt[(dq + 2) * 196 + row] = vv.z; Vt[(dq + 3) * 196 + row] = vv.w;
    }
    __syncthreads();

    float accS[12][4];
#pragma unroll
    for (int i = 0; i < 12; i++)
#pragma unroll
        for (int j = 0; j < 4; j++) accS[i][j] = 0.f;

#pragma unroll
    for (int ks = 0; ks < 8; ks++) {
        int kk = ks * 8;
        unsigned a[4];
        ldm_x4(a[0], a[1], a[2], a[3], &Qs[(wm * 16 + aRow) * 68 + kk + aCol]);
#pragma unroll
        for (int ng = 0; ng < 3; ng++) {
            int n0 = wn * 96 + ng * 32;
            unsigned bL[4], bH[4];
            ldm_x4(bL[0], bL[1], bL[2], bL[3], &Ks[(n0 + lane) * 68 + kk]);
            ldm_x4(bH[0], bH[1], bH[2], bH[3], &Ks[(n0 + lane) * 68 + kk + 4]);
#pragma unroll
            for (int t2 = 0; t2 < 4; t2++) {
                unsigned bb[2] = { bL[t2], bH[t2] };
                mma_tf32(accS[ng * 4 + t2], a, bb);
            }
        }
    }

    int r0 = wm * 16 + gid, r1 = r0 + 8;
    size_t qr0 = ((size_t)(b * TP + cs + r0) * HH + h) * 383;
    size_t qr1 = ((size_t)(b * TP + cs + r1) * HH + h) * 383;
#pragma unroll
    for (int nt = 0; nt < 12; nt++) {
        int c0 = wn * 96 + nt * 8 + tig * 2;
        int c1 = c0 + 1;
        int k0g = cs - 128 + c0;
        int k1g = k0g + 1;
        S[r0 * 196 + c0] = (k0g < lim) ? (accS[nt][0] + __ldg(&qrel[qr0 + 319 + r0 - c0])) : NEGINF;
        S[r0 * 196 + c1] = (k1g < lim) ? (accS[nt][1] + __ldg(&qrel[qr0 + 319 + r0 - c1])) : NEGINF;
        S[r1 * 196 + c0] = (k0g < lim) ? (accS[nt][2] + __ldg(&qrel[qr1 + 319 + r1 - c0])) : NEGINF;
        S[r1 * 196 + c1] = (k1g < lim) ? (accS[nt][3] + __ldg(&qrel[qr1 + 319 + r1 - c1])) : NEGINF;
    }
    __syncthreads();

#pragma unroll
    for (int rw = 0; rw < 8; rw++) {
        int r = wid * 8 + rw;
        float sv[6];
        float m = NEGINF;
#pragma unroll
        for (int t = 0; t < 6; t++) { sv[t] = S[r * 196 + lane + t * 32]; m = fmaxf(m, sv[t]); }
#pragma unroll
        for (int o = 16; o > 0; o >>= 1) m = fmaxf(m, __shfl_xor_sync(0xffffffffu, m, o));
        float ss = 0.f;
#pragma unroll
        for (int t = 0; t < 6; t++) { sv[t] = expf(sv[t] - m); ss += sv[t]; }
#pragma unroll
        for (int o = 16; o > 0; o >>= 1) ss += __shfl_xor_sync(0xffffffffu, ss, o);
        float inv = 1.f / ss;
#pragma unroll
        for (int t = 0; t < 6; t++) S[r * 196 + lane + t * 32] = sv[t] * inv;
    }
    __syncthreads();

    float accO[4][4];
#pragma unroll
    for (int i = 0; i < 4; i++)
#pragma unroll
        for (int j = 0; j < 4; j++) accO[i][j] = 0.f;

#pragma unroll
    for (int ks = 0; ks < 24; ks++) {
        int kk = ks * 8;
        unsigned a[4], bL[4], bH[4];
        ldm_x4(a[0], a[1], a[2], a[3], &S[(wm * 16 + aRow) * 196 + kk + aCol]);
        ldm_x4(bL[0], bL[1], bL[2], bL[3], &Vt[(wn * 32 + lane) * 196 + kk]);
        ldm_x4(bH[0], bH[1], bH[2], bH[3], &Vt[(wn * 32 + lane) * 196 + kk + 4]);
#pragma unroll
        for (int nt = 0; nt < 4; nt++) {
            unsigned bb[2] = { bL[nt], bH[nt] };
            mma_tf32(accO[nt], a, bb);
        }
    }

    int q0 = cs + r0, q1 = cs + r1;
#pragma unroll
    for (int nt = 0; nt < 4; nt++) {
        int d0 = wn * 32 + nt * 8 + tig * 2;
        if (q0 < lim) {
            float* op = ob + ((size_t)(b * TT + q0 - 128)) * DD + h * 64 + d0;
            op[0] = accO[nt][0]; op[1] = accO[nt][1];
        }
        if (q1 < lim) {
            float* op = ob + ((size_t)(b * TT + q1 - 128)) * DD + h * 64 + d0;
            op[0] = accO[nt][2]; op[1] = accO[nt][3];
        }
    }
}

// ---------------- Dense flash attention (invalid rows), tf32 tensor cores ----------------
__global__ __launch_bounds__(256) void dense_flash(
    const float* __restrict__ qb, const float* __restrict__ kv,
    const float* __restrict__ qrel, const int* __restrict__ alen,
    float* __restrict__ ob)
{
    extern __shared__ float sm[];
    float* Qs = sm;                    // 64*68
    float* Ks = Qs + 64 * 68;          // 128*68
    float* Vt = Ks + 128 * 68;         // 64*132
    float* S  = Vt + 64 * 132;         // 64*132
    float* rowm = S + 64 * 132;
    float* rowsum = rowm + 64;
    float* rowscale = rowsum + 64;

    int c = blockIdx.x + 2;
    int h = blockIdx.y;
    int b = blockIdx.z;
    int cs = c * 64;
    int lim = alen[b] + LCW;
    if (cs + 64 <= lim) return;
    int tid = threadIdx.x;
    int g = h >> 2;
    int lane = tid & 31, wid = tid >> 5;
    int wm = wid & 3, wn = wid >> 2;
    int gid = lane >> 2, tig = lane & 3;
    int aRow = lane & 15, aCol = (lane < 16) ? 0 : 4;
    int r0 = wm * 16 + gid, r1 = r0 + 8;

    const float* qbase = qb + ((size_t)(b * TP + cs)) * DD + h * 64;
#pragma unroll
    for (int i = 0; i < 4; i++) {
        int e = tid + i * 256;
        int row = e >> 4, dq = (e & 15) * 4;
        float4 v = *(const float4*)(qbase + (size_t)row * DD + dq);
        Qs[row * 68 + dq + 0] = v.x; Qs[row * 68 + dq + 1] = v.y;
        Qs[row * 68 + dq + 2] = v.z; Qs[row * 68 + dq + 3] = v.w;
    }
    if (tid < 64) { rowm[tid] = NEGINF; rowsum[tid] = 0.f; }

    float accO[4][4];
#pragma unroll
    for (int i = 0; i < 4; i++)
#pragma unroll
        for (int j = 0; j < 4; j++) accO[i][j] = 0.f;

    size_t qr0 = ((size_t)(b * TP + cs + r0) * HH + h) * 383;
    size_t qr1 = ((size_t)(b * TP + cs + r1) * HH + h) * 383;

    __syncthreads();

    for (int pg = 0; pg < 9; pg++) {
        const float* kp = kv + ((size_t)(b * TP + pg * 128)) * 256 + g * 64;
#pragma unroll
        for (int i = 0; i < 8; i++) {
            int e = tid + i * 256;
            int row = e >> 4, dq = (e & 15) * 4;
            float4 kk = *(const float4*)(kp + (size_t)row * 256 + dq);
            Ks[row * 68 + dq + 0] = kk.x; Ks[row * 68 + dq + 1] = kk.y;
            Ks[row * 68 + dq + 2] = kk.z; Ks[row * 68 + dq + 3] = kk.w;
            float4 vv = *(const float4*)(kp + (size_t)row * 256 + 128 + dq);
            Vt[(dq + 0) * 132 + row] = vv.x; Vt[(dq + 1) * 132 + row] = vv.y;
            Vt[(dq + 2) * 132 + row] = vv.z; Vt[(dq + 3) * 132 + row] = vv.w;
        }
        __syncthreads();

        float accS[8][4];
#pragma unroll
        for (int i = 0; i < 8; i++)
#pragma unroll
            for (int j = 0; j < 4; j++) accS[i][j] = 0.f;
#pragma unroll
        for (int ks = 0; ks < 8; ks++) {
            int kk = ks * 8;
            unsigned a[4];
            ldm_x4(a[0], a[1], a[2], a[3], &Qs[(wm * 16 + aRow) * 68 + kk + aCol]);
#pragma unroll
            for (int ng = 0; ng < 2; ng++) {
                int n0 = wn * 64 + ng * 32;
                unsigned bL[4], bH[4];
                ldm_x4(bL[0], bL[1], bL[2], bL[3], &Ks[(n0 + lane) * 68 + kk]);
                ldm_x4(bH[0], bH[1], bH[2], bH[3], &Ks[(n0 + lane) * 68 + kk + 4]);
#pragma unroll
                for (int t2 = 0; t2 < 4; t2++) {
                    unsigned bb[2] = { bL[t2], bH[t2] };
                    mma_tf32(accS[ng * 4 + t2], a, bb);
                }
            }
        }
#pragma unroll
        for (int nt = 0; nt < 8; nt++) {
            int c0 = wn * 64 + nt * 8 + tig * 2;
            int c1 = c0 + 1;
            int k0 = pg * 128 + c0, k1 = k0 + 1;
            int d00 = max(-191, min(191, cs + r0 - k0));
            int d01 = max(-191, min(191, cs + r0 - k1));
            int d10 = max(-191, min(191, cs + r1 - k0));
            int d11 = max(-191, min(191, cs + r1 - k1));
            S[r0 * 132 + c0] = accS[nt][0] + __ldg(&qrel[qr0 + 191 + d00]);
            S[r0 * 132 + c1] = accS[nt][1] + __ldg(&qrel[qr0 + 191 + d01]);
            S[r1 * 132 + c0] = accS[nt][2] + __ldg(&qrel[qr1 + 191 + d10]);
            S[r1 * 132 + c1] = accS[nt][3] + __ldg(&qrel[qr1 + 191 + d11]);
        }
        __syncthreads();

#pragma unroll
        for (int rw = 0; rw < 8; rw++) {
            int r = wid * 8 + rw;
            float v0 = S[r * 132 + lane];
            float v1 = S[r * 132 + lane + 32];
            float v2 = S[r * 132 + lane + 64];
            float v3 = S[r * 132 + lane + 96];
            float mn = fmaxf(fmaxf(v0, v1), fmaxf(v2, v3));
#pragma unroll
            for (int o = 16; o > 0; o >>= 1) mn = fmaxf(mn, __shfl_xor_sync(0xffffffffu, mn, o));
            float mo = rowm[r];
            float mp = fmaxf(mo, mn);
            float p0 = expf(v0 - mp), p1 = expf(v1 - mp), p2 = expf(v2 - mp), p3 = expf(v3 - mp);
            S[r * 132 + lane] = p0; S[r * 132 + lane + 32] = p1;
            S[r * 132 + lane + 64] = p2; S[r * 132 + lane + 96] = p3;
            float ss = p0 + p1 + p2 + p3;
#pragma unroll
            for (int o = 16; o > 0; o >>= 1) ss += __shfl_xor_sync(0xffffffffu, ss, o);
            if (lane == 0) {
                float scale = expf(mo - mp);
                rowm[r] = mp;
                rowscale[r] = scale;
                rowsum[r] = rowsum[r] * scale + ss;
            }
        }
        __syncthreads();

        float sc0 = rowscale[r0], sc1 = rowscale[r1];
#pragma unroll
        for (int nt = 0; nt < 4; nt++) {
            accO[nt][0] *= sc0; accO[nt][1] *= sc0;
            accO[nt][2] *= sc1; accO[nt][3] *= sc1;
        }
#pragma unroll
        for (int ks = 0; ks < 16; ks++) {
            int kk = ks * 8;
            unsigned a[4], bL[4], bH[4];
            ldm_x4(a[0], a[1], a[2], a[3], &S[(wm * 16 + aRow) * 132 + kk + aCol]);
            ldm_x4(bL[0], bL[1], bL[2], bL[3], &Vt[(wn * 32 + lane) * 132 + kk]);
            ldm_x4(bH[0], bH[1], bH[2], bH[3], &Vt[(wn * 32 + lane) * 132 + kk + 4]);
#pragma unroll
            for (int nt = 0; nt < 4; nt++) {
                unsigned bb[2] = { bL[nt], bH[nt] };
                mma_tf32(accO[nt], a, bb);
            }
        }
        __syncthreads();
    }

    int q0 = cs + r0, q1 = cs + r1;
    float inv0 = 1.f / rowsum[r0];
    float inv1 = 1.f / rowsum[r1];
#pragma unroll
    for (int nt = 0; nt < 4; nt++) {
        int d0 = wn * 32 + nt * 8 + tig * 2;
        if (q0 >= lim) {
            float* op = ob + ((size_t)(b * TT + q0 - 128)) * DD + h * 64 + d0;
            op[0] = accO[nt][0] * inv0; op[1] = accO[nt][1] * inv0;
        }
        if (q1 >= lim) {
            float* op = ob + ((size_t)(b * TT + q1 - 128)) * DD + h * 64 + d0;
            op[0] = accO[nt][2] * inv1; op[1] = accO[nt][3] * inv1;
        }
    }
}

// ---------------- depthwise conv (k=9, pad 4) + SiLU ----------------
__global__ __launch_bounds__(128) void dwconv_silu(
    const float* __restrict__ in, const float* __restrict__ dw, float* __restrict__ out)
{
    int t = blockIdx.x, b = blockIdx.y;
    int d0 = threadIdx.x * 4;
    float w[9][4];
#pragma unroll
    for (int c = 0; c < 4; c++)
#pragma unroll
        for (int j = 0; j < 9; j++)
            w[j][c] = __ldg(&dw[(d0 + c) * 9 + j]);
    float4 acc = make_float4(0.f, 0.f, 0.f, 0.f);
#pragma unroll
    for (int j = 0; j < 9; j++) {
        int tt = t + j - 4;
        if (tt >= 0 && tt < TT) {
            float4 v = *(const float4*)(in + ((size_t)(b * TT + tt)) * DD + d0);
            acc.x += v.x * w[j][0];
            acc.y += v.y * w[j][1];
            acc.z += v.z * w[j][2];
            acc.w += v.w * w[j][3];
        }
    }
    acc.x = acc.x / (1.f + expf(-acc.x));
    acc.y = acc.y / (1.f + expf(-acc.y));
    acc.z = acc.z / (1.f + expf(-acc.z));
    acc.w = acc.w / (1.f + expf(-acc.w));
    *(float4*)(out + ((size_t)(b * TT + t)) * DD + d0) = acc;
}

// ---------------- orchestration ----------------
extern "C" void kernel_launch(void* const* d_in, const int* in_sizes, int n_in,
                              void* d_out, int out_size)
{
    const float* x_in  = (const float*)d_in[0];
    const int*   alen  = (const int*)d_in[1];
    const float* ln1_w = (const float*)d_in[2];
    const float* ln1_b = (const float*)d_in[3];
    const float* wq    = (const float*)d_in[4];
    const float* wk    = (const float*)d_in[5];
    const float* wv    = (const float*)d_in[6];
    const float* wo    = (const float*)d_in[7];
    const float* rel   = (const float*)d_in[8];
    const float* ln2_w = (const float*)d_in[9];
    const float* ln2_b = (const float*)d_in[10];
    const float* pw1   = (const float*)d_in[11];
    const float* dw    = (const float*)d_in[12];
    const float* pw2   = (const float*)d_in[13];
    const float* ln3_w = (const float*)d_in[14];
    const float* ln3_b = (const float*)d_in[15];
    const float* w1    = (const float*)d_in[16];
    const float* w2    = (const float*)d_in[17];

    float* scr = nullptr;
    cudaGetSymbolAddress((void**)&scr, g_scr);
    float* xpad  = scr + OFF_XPAD;
    float* xbuf  = scr + OFF_XBUF;
    float* ybuf  = scr + OFF_YBUF;
    float* qbuf  = scr + OFF_QBUF;
    float* kvbuf = scr + OFF_KVBUF;
    float* qrlb  = scr + OFF_QREL;
    float* obuf  = scr + OFF_OBUF;
    float* hbuf  = scr + OFF_HBUF;
    float* gbuf  = scr + OFF_GBUF;
    float* kvw   = scr + OFF_KVW;
    float* pw1p  = scr + OFF_PW1P;
    float* w1p   = scr + OFF_W1P;

    const int WIN_SMEM = (64 * 68 + 192 * 68 + 64 * 196 + 64 * 196) * 4;
    const int DF_SMEM  = (64 * 68 + 128 * 68 + 64 * 132 + 64 * 132 + 192) * 4;
    cudaFuncSetAttribute(win_attn, cudaFuncAttributeMaxDynamicSharedMemorySize, WIN_SMEM);
    cudaFuncSetAttribute(dense_flash, cudaFuncAttributeMaxDynamicSharedMemorySize, DF_SMEM);

    zero_pad_kernel<<<(BB * LCW * DD + 255) / 256, 256>>>(xpad);
    pack_kv<<<(4 * 256 * 512 + 255) / 256, 256>>>(wk, wv, kvw);
    pack_glu<<<(4 * 1024 * 512 + 255) / 256, 256>>>(pw1, pw1p, 512, 4 * 1024 * 512);
    pack_glu<<<(4 * 2048 * 512 + 255) / 256, 256>>>(w1, w1p, 1024, 4 * 2048 * 512);

    for (int l = 0; l < 4; l++) {
        const float* src = (l == 0) ? x_in : xbuf;
        ln_kernel<<<4096, 128>>>(src, ln1_w + l * 512, ln1_b + l * 512, ybuf, xpad);
        gemm_tc<<<dim3(8, 36), 256>>>(xpad, wq + (size_t)l * 512 * 512, qbuf, nullptr, 4608, 512, 512, 0.125f, 0);
        gemm_tc<<<dim3(4, 36), 256>>>(xpad, kvw + (size_t)l * 256 * 512, kvbuf, nullptr, 4608, 256, 512, 1.f, 0);
        gemm_tc<<<dim3(6, 288), 256>>>(qbuf, rel + (size_t)l * 383 * 64, qrlb, nullptr, 36864, 383, 64, 1.f, 0);
        win_attn<<<dim3(16, 8, 4), 256, WIN_SMEM>>>(qbuf, kvbuf, qrlb, alen, obuf);
        dense_flash<<<dim3(16, 8, 4), 256, DF_SMEM>>>(qbuf, kvbuf, qrlb, alen, obuf);
        gemm_tc<<<dim3(8, 32), 256>>>(obuf, wo + (size_t)l * 512 * 512, xbuf, ybuf, 4096, 512, 512, 1.f, 0);
        ln_kernel<<<4096, 128>>>(xbuf, ln2_w + l * 512, ln2_b + l * 512, ybuf, nullptr);
        gemm_tc<<<dim3(16, 32), 256>>>(ybuf, pw1p + (size_t)l * 1024 * 512, gbuf, nullptr, 4096, 1024, 512, 1.f, 1);
        dwconv_silu<<<dim3(1024, 4), 128>>>(gbuf, dw + (size_t)l * 512 * 9, hbuf);
        gemm_tc<<<dim3(8, 32), 256>>>(hbuf, pw2 + (size_t)l * 512 * 512, xbuf, ybuf, 4096, 512, 512, 1.f, 0);
        ln_kernel<<<4096, 128>>>(xbuf, ln3_w + l * 512, ln3_b + l * 512, ybuf, nullptr);
        gemm_tc<<<dim3(32, 32), 256>>>(ybuf, w1p + (size_t)l * 2048 * 512, gbuf, nullptr, 4096, 2048, 512, 1.f, 2);
        float* dst = (l == 3) ? (float*)d_out : xbuf;
        gemm_tc<<<dim3(8, 32), 256>>>(gbuf, w2 + (size_t)l * 512 * 1024, dst, ybuf, 4096, 512, 1024, 1.f, 0);
    }
}